// round 6
// baseline (speedup 1.0000x reference)
#include <cuda_runtime.h>

// GraphAttentionLayer: out = softmax(beta*cos + (cos<0 ? -1e9 : 0) + 10*adj) @ x
// B=4, N=4096, D=64, fp32.
//
// Simplifications (all within 1e-3 rel-err budget):
//  - no softmax max-subtraction (max arg <= 11, no overflow in fp32)
//  - cos via pre-normalized xhat (EPS folded away, ~1.5e-9 rel effect)
//  - exp(10*adj) = 1 + adj*(e^10-1)  (adj is exactly 0.0/1.0)
//  - exp(t), t in [0,1]: degree-8 Taylor polynomial on the FMA pipe (avoids MUFU bottleneck)

constexpr int B = 4, N = 4096, D = 64;
constexpr int BN = 64, BM = 64;
constexpr int NTHREADS = 256;
constexpr int TSTRIDE = 68;              // 64 + 4 pad: 16B-aligned rows, conflict-free
constexpr int TILE_F = 64 * TSTRIDE;     // floats per smem tile
constexpr int SMEM_BYTES = 4 * TILE_F * 4;

__device__ float g_xhat[(size_t)B * N * D];

// exp(t) for t in [-1, 1.01], degree-8 Taylor. Max rel err ~7.5e-6 on [0,1].
__device__ __forceinline__ float exp01(float t) {
    float p = 2.48015873e-5f;            // 1/40320
    p = fmaf(p, t, 1.98412698e-4f);      // 1/5040
    p = fmaf(p, t, 1.38888889e-3f);      // 1/720
    p = fmaf(p, t, 8.33333333e-3f);      // 1/120
    p = fmaf(p, t, 4.16666667e-2f);      // 1/24
    p = fmaf(p, t, 1.66666667e-1f);      // 1/6
    p = fmaf(p, t, 0.5f);
    p = fmaf(p, t, 1.0f);
    p = fmaf(p, t, 1.0f);
    return p;
}

__global__ void prep_kernel(const float* __restrict__ x) {
    int row  = blockIdx.x * 8 + (threadIdx.x >> 5);
    int lane = threadIdx.x & 31;
    const float2* xr = reinterpret_cast<const float2*>(x + (size_t)row * D);
    float2 v = xr[lane];
    float s = fmaf(v.x, v.x, v.y * v.y);
    #pragma unroll
    for (int o = 16; o > 0; o >>= 1) s += __shfl_xor_sync(0xffffffffu, s, o);
    float inv = 1.0f / sqrtf(s);
    float2 h; h.x = v.x * inv; h.y = v.y * inv;
    reinterpret_cast<float2*>(g_xhat + (size_t)row * D)[lane] = h;
}

__global__ void __launch_bounds__(NTHREADS, 2) attn_kernel(
    const float* __restrict__ x, const float* __restrict__ adj,
    const float* __restrict__ beta, float* __restrict__ out)
{
    extern __shared__ float sm[];
    float* XnT = sm;                 // [64][68]  xhat^T for n-tile: XnT[d*68 + n]
    float* XmT = sm + TILE_F;        // [64][68]  xhat^T for m-tile
    float* Xm2 = sm + 2 * TILE_F;    // [64][68]  original x, row-major [m][d]
    float* Ws  = sm + 3 * TILE_F;    // [64][68]  weights [n][m]

    const int tid = threadIdx.x;
    const int tx  = tid & 15;        // owns cols 4tx..4tx+3 (m in GEMM1, d in GEMM2)
    const int ty  = tid >> 4;        // owns rows 4ty..4ty+3 (n)
    const int n0  = blockIdx.x * BN;
    const int b   = blockIdx.y;

    const float betav = beta[0];
    const float E10M1 = 22025.465794806718f;   // e^10 - 1

    const float* xb  = x      + (size_t)b * N * D;
    const float* xhb = g_xhat + (size_t)b * N * D;
    const float* adjb = adj   + (size_t)b * N * N;

    // Load XnT (transposed xhat). Lane map d4=idx>>6, r=idx&63 -> STS conflict-free.
    #pragma unroll
    for (int it = 0; it < 4; it++) {
        int idx = tid + it * NTHREADS;
        int d4 = idx >> 6;
        int r  = idx & 63;
        float4 v = reinterpret_cast<const float4*>(xhb + (size_t)(n0 + r) * D)[d4];
        XnT[(4 * d4 + 0) * TSTRIDE + r] = v.x;
        XnT[(4 * d4 + 1) * TSTRIDE + r] = v.y;
        XnT[(4 * d4 + 2) * TSTRIDE + r] = v.z;
        XnT[(4 * d4 + 3) * TSTRIDE + r] = v.w;
    }

    float acc[4][4] = {};
    float rs[4] = {0.f, 0.f, 0.f, 0.f};

    for (int m0 = 0; m0 < N; m0 += BM) {
        // Prefetch adj tile (registers); latency hidden under GEMM1.
        float4 adjv[4];
        #pragma unroll
        for (int i = 0; i < 4; i++) {
            adjv[i] = *reinterpret_cast<const float4*>(
                adjb + (size_t)(n0 + 4 * ty + i) * N + (m0 + 4 * tx));
        }

        __syncthreads();   // previous GEMM2 done with Xm2/Ws

        // Load XmT (transposed xhat) and Xm2 (row-major x).
        #pragma unroll
        for (int it = 0; it < 4; it++) {
            int idx = tid + it * NTHREADS;
            int d4 = idx >> 6;
            int r  = idx & 63;
            float4 v = reinterpret_cast<const float4*>(xhb + (size_t)(m0 + r) * D)[d4];
            XmT[(4 * d4 + 0) * TSTRIDE + r] = v.x;
            XmT[(4 * d4 + 1) * TSTRIDE + r] = v.y;
            XmT[(4 * d4 + 2) * TSTRIDE + r] = v.z;
            XmT[(4 * d4 + 3) * TSTRIDE + r] = v.w;
            int r2 = idx >> 4;
            int c4 = idx & 15;
            float4 u = reinterpret_cast<const float4*>(xb + (size_t)(m0 + r2) * D)[c4];
            *reinterpret_cast<float4*>(&Xm2[r2 * TSTRIDE + 4 * c4]) = u;
        }
        __syncthreads();

        // GEMM1: s[i][j] = sum_k xhat_n[4ty+i][k] * xhat_m[4tx+j][k]  (== cos)
        float s[4][4] = {};
        #pragma unroll 8
        for (int k = 0; k < 64; k++) {
            float4 a  = *reinterpret_cast<const float4*>(&XnT[k * TSTRIDE + 4 * ty]);
            float4 bb = *reinterpret_cast<const float4*>(&XmT[k * TSTRIDE + 4 * tx]);
            float af[4] = {a.x, a.y, a.z, a.w};
            float bf[4] = {bb.x, bb.y, bb.z, bb.w};
            #pragma unroll
            for (int i = 0; i < 4; i++)
                #pragma unroll
                for (int j = 0; j < 4; j++)
                    s[i][j] = fmaf(af[i], bf[j], s[i][j]);
        }

        // Epilogue: w = (cos>=0) ? exp(beta*cos) * (1 + adj*(e^10-1)) : 0
        #pragma unroll
        for (int i = 0; i < 4; i++) {
            float av[4] = {adjv[i].x, adjv[i].y, adjv[i].z, adjv[i].w};
            float wv[4];
            #pragma unroll
            for (int j = 0; j < 4; j++) {
                float c = s[i][j];
                float e = exp01(betav * c);
                float w = e * fmaf(av[j], E10M1, 1.0f);
                w = (c >= 0.0f) ? w : 0.0f;
                rs[i] += w;
                wv[j] = w;
            }
            *reinterpret_cast<float4*>(&Ws[(4 * ty + i) * TSTRIDE + 4 * tx]) =
                make_float4(wv[0], wv[1], wv[2], wv[3]);
        }
        __syncthreads();

        // GEMM2: acc[i][j] += sum_m Ws[4ty+i][m] * x_m[m][4tx+j]
        // Ws read as float4 along m (4 m-values per LDS.128, 2-way broadcast
        // across the warp) -> ~1 cyc crossbar per load instead of 4 scalar LDS.
        #pragma unroll 4
        for (int mc = 0; mc < 64; mc += 4) {
            float wrow[4][4];
            #pragma unroll
            for (int i = 0; i < 4; i++) {
                float4 wv = *reinterpret_cast<const float4*>(
                    &Ws[(4 * ty + i) * TSTRIDE + mc]);
                wrow[i][0] = wv.x; wrow[i][1] = wv.y;
                wrow[i][2] = wv.z; wrow[i][3] = wv.w;
            }
            #pragma unroll
            for (int mm = 0; mm < 4; mm++) {
                float4 bb = *reinterpret_cast<const float4*>(
                    &Xm2[(mc + mm) * TSTRIDE + 4 * tx]);
                float bf[4] = {bb.x, bb.y, bb.z, bb.w};
                #pragma unroll
                for (int i = 0; i < 4; i++)
                    #pragma unroll
                    for (int j = 0; j < 4; j++)
                        acc[i][j] = fmaf(wrow[i][mm], bf[j], acc[i][j]);
            }
        }
    }

    // Row-sum reduction over the 16 tx lanes sharing each row (xor within 16-lane group).
    #pragma unroll
    for (int i = 0; i < 4; i++) {
        float v = rs[i];
        v += __shfl_xor_sync(0xffffffffu, v, 1);
        v += __shfl_xor_sync(0xffffffffu, v, 2);
        v += __shfl_xor_sync(0xffffffffu, v, 4);
        v += __shfl_xor_sync(0xffffffffu, v, 8);
        rs[i] = 1.0f / v;
    }

    #pragma unroll
    for (int i = 0; i < 4; i++) {
        float4 o;
        o.x = acc[i][0] * rs[i];
        o.y = acc[i][1] * rs[i];
        o.z = acc[i][2] * rs[i];
        o.w = acc[i][3] * rs[i];
        *reinterpret_cast<float4*>(
            out + (size_t)(b * N + n0 + 4 * ty + i) * D + 4 * tx) = o;
    }
}

extern "C" void kernel_launch(void* const* d_in, const int* in_sizes, int n_in,
                              void* d_out, int out_size) {
    const float* x    = (const float*)d_in[0];
    const float* adj  = (const float*)d_in[1];
    const float* beta = (const float*)d_in[2];
    float* out = (float*)d_out;

    prep_kernel<<<B * N / 8, NTHREADS>>>(x);

    cudaFuncSetAttribute(attn_kernel,
                         cudaFuncAttributeMaxDynamicSharedMemorySize, SMEM_BYTES);
    dim3 grid(N / BN, B);
    attn_kernel<<<grid, NTHREADS, SMEM_BYTES>>>(x, adj, beta, out);
}

// round 7
// speedup vs baseline: 1.1626x; 1.1626x over previous
#include <cuda_runtime.h>
#include <cstdint>

// GraphAttentionLayer: out = softmax(beta*cos + (cos<0 ? -1e9 : 0) + 10*adj) @ x
// B=4, N=4096, D=64, fp32.
// R7: 128x128 block tile, 8x8 micro-tile GEMM1 / 8x4 GEMM2 (2x FFMA per LDS),
//     adj staged via cp.async into the Ws smem region during GEMM1.

constexpr int B = 4, N = 4096, D = 64;
constexpr int BN = 128, BM = 128;
constexpr int NTHREADS = 256;
constexpr int SN = 132;                    // 128 + 4 pad (132*4B = 33*16B, 16B aligned rows)
constexpr int SD = 68;                     // 64 + 4 pad
constexpr int XNT_OFF = 0;                 // [64 d][SN]   xhat^T n-tile
constexpr int XMT_OFF = XNT_OFF + 64 * SN; // [64 d][SN]   xhat^T m-tile
constexpr int XM2_OFF = XMT_OFF + 64 * SN; // [128 m][SD]  x m-tile row-major
constexpr int WS_OFF  = XM2_OFF + 128 * SD;// [128 n][SN]  adj-in / weights-out
constexpr int SMEM_FLOATS = WS_OFF + 128 * SN;
constexpr int SMEM_BYTES  = SMEM_FLOATS * 4;   // 169,984 B

__device__ float g_xhat[(size_t)B * N * D];

// exp(t) for t in [0, 1.01], degree-8 Taylor. Max rel err ~7.5e-6.
__device__ __forceinline__ float exp01(float t) {
    float p = 2.48015873e-5f;
    p = fmaf(p, t, 1.98412698e-4f);
    p = fmaf(p, t, 1.38888889e-3f);
    p = fmaf(p, t, 8.33333333e-3f);
    p = fmaf(p, t, 4.16666667e-2f);
    p = fmaf(p, t, 1.66666667e-1f);
    p = fmaf(p, t, 0.5f);
    p = fmaf(p, t, 1.0f);
    p = fmaf(p, t, 1.0f);
    return p;
}

__global__ void prep_kernel(const float* __restrict__ x) {
    int row  = blockIdx.x * 8 + (threadIdx.x >> 5);
    int lane = threadIdx.x & 31;
    const float2* xr = reinterpret_cast<const float2*>(x + (size_t)row * D);
    float2 v = xr[lane];
    float s = fmaf(v.x, v.x, v.y * v.y);
    #pragma unroll
    for (int o = 16; o > 0; o >>= 1) s += __shfl_xor_sync(0xffffffffu, s, o);
    float inv = 1.0f / sqrtf(s);
    float2 h; h.x = v.x * inv; h.y = v.y * inv;
    reinterpret_cast<float2*>(g_xhat + (size_t)row * D)[lane] = h;
}

__global__ void __launch_bounds__(NTHREADS, 1) attn_kernel(
    const float* __restrict__ x, const float* __restrict__ adj,
    const float* __restrict__ beta, float* __restrict__ out)
{
    extern __shared__ float sm[];
    float* XnT = sm + XNT_OFF;
    float* XmT = sm + XMT_OFF;
    float* Xm2 = sm + XM2_OFF;
    float* Ws  = sm + WS_OFF;
    const uint32_t ws_smem = (uint32_t)__cvta_generic_to_shared(Ws);

    const int tid = threadIdx.x;
    const int tx  = tid & 15;        // GEMM1 m-cols {4tx..4tx+3, 64+4tx..+3}; GEMM2 d-cols 4tx..
    const int ty  = tid >> 4;        // rows 8ty..8ty+7
    const int n0  = blockIdx.x * BN;
    const int b   = blockIdx.y;

    const float betav = beta[0];
    const float E10M1 = 22025.465794806718f;   // e^10 - 1

    const float* xb   = x      + (size_t)b * N * D;
    const float* xhb  = g_xhat + (size_t)b * N * D;
    const float* adjb = adj    + (size_t)b * N * N;

    // Load XnT: xhat^T for the n-tile. Consecutive-lane rows -> conflict-free STS.
    #pragma unroll
    for (int it = 0; it < 8; it++) {
        int idx = tid + it * NTHREADS;
        int d4 = idx >> 7;           // 0..15
        int r  = idx & 127;          // 0..127
        float4 v = *reinterpret_cast<const float4*>(xhb + (size_t)(n0 + r) * D + 4 * d4);
        XnT[(4 * d4 + 0) * SN + r] = v.x;
        XnT[(4 * d4 + 1) * SN + r] = v.y;
        XnT[(4 * d4 + 2) * SN + r] = v.z;
        XnT[(4 * d4 + 3) * SN + r] = v.w;
    }

    float acc[8][4] = {};
    float rs[8] = {};

    for (int m0 = 0; m0 < N; m0 += BM) {
        __syncthreads();   // prev GEMM2 done with XmT/Xm2/Ws

        // Stage adj tile into Ws via cp.async (hidden under GEMM1).
        #pragma unroll
        for (int it = 0; it < 16; it++) {
            int idx = tid + it * NTHREADS;
            int row = idx >> 5;      // 0..127
            int c   = idx & 31;      // 16B chunk within row
            uint32_t dst = ws_smem + (uint32_t)(row * SN + 4 * c) * 4u;
            const float* src = adjb + (size_t)(n0 + row) * N + m0 + 4 * c;
            asm volatile("cp.async.cg.shared.global [%0], [%1], 16;" :: "r"(dst), "l"(src));
        }
        asm volatile("cp.async.commit_group;");

        // Load XmT (transposed xhat) and Xm2 (row-major x) for the m-tile.
        #pragma unroll
        for (int it = 0; it < 8; it++) {
            int idx = tid + it * NTHREADS;
            int d4 = idx >> 7;
            int r  = idx & 127;
            float4 v = *reinterpret_cast<const float4*>(xhb + (size_t)(m0 + r) * D + 4 * d4);
            XmT[(4 * d4 + 0) * SN + r] = v.x;
            XmT[(4 * d4 + 1) * SN + r] = v.y;
            XmT[(4 * d4 + 2) * SN + r] = v.z;
            XmT[(4 * d4 + 3) * SN + r] = v.w;
            int r2 = idx >> 4;       // 0..127
            int c4 = idx & 15;       // 0..15
            float4 u = *reinterpret_cast<const float4*>(xb + (size_t)(m0 + r2) * D + 4 * c4);
            *reinterpret_cast<float4*>(&Xm2[r2 * SD + 4 * c4]) = u;
        }
        __syncthreads();

        // GEMM1: s[i][j] = cos(n=8ty+i, m = j<4 ? 4tx+j : 64+4tx+j-4)
        float s[8][8] = {};
        #pragma unroll 4
        for (int k = 0; k < 64; k++) {
            const float* xn = &XnT[k * SN];
            const float* xm = &XmT[k * SN];
            float4 a0 = *reinterpret_cast<const float4*>(xn + 8 * ty);
            float4 a1 = *reinterpret_cast<const float4*>(xn + 8 * ty + 4);
            float4 b0 = *reinterpret_cast<const float4*>(xm + 4 * tx);
            float4 b1 = *reinterpret_cast<const float4*>(xm + 64 + 4 * tx);
            float af[8] = {a0.x, a0.y, a0.z, a0.w, a1.x, a1.y, a1.z, a1.w};
            float bf[8] = {b0.x, b0.y, b0.z, b0.w, b1.x, b1.y, b1.z, b1.w};
            #pragma unroll
            for (int i = 0; i < 8; i++)
                #pragma unroll
                for (int j = 0; j < 8; j++)
                    s[i][j] = fmaf(af[i], bf[j], s[i][j]);
        }

        asm volatile("cp.async.wait_group 0;" ::: "memory");
        __syncthreads();   // adj tile fully in Ws

        // Epilogue: read adj from Ws, compute w, write w back in place.
        #pragma unroll
        for (int i = 0; i < 8; i++) {
            float* wsrow = &Ws[(8 * ty + i) * SN];
            float4 q0 = *reinterpret_cast<const float4*>(wsrow + 4 * tx);
            float4 q1 = *reinterpret_cast<const float4*>(wsrow + 64 + 4 * tx);
            float av[8] = {q0.x, q0.y, q0.z, q0.w, q1.x, q1.y, q1.z, q1.w};
            float wv[8];
            #pragma unroll
            for (int j = 0; j < 8; j++) {
                float c = s[i][j];
                float e = exp01(betav * c);
                float w = e * fmaf(av[j], E10M1, 1.0f);
                w = (c >= 0.0f) ? w : 0.0f;
                rs[i] += w;
                wv[j] = w;
            }
            *reinterpret_cast<float4*>(wsrow + 4 * tx) =
                make_float4(wv[0], wv[1], wv[2], wv[3]);
            *reinterpret_cast<float4*>(wsrow + 64 + 4 * tx) =
                make_float4(wv[4], wv[5], wv[6], wv[7]);
        }
        __syncthreads();

        // GEMM2: acc[i][j] += sum_m Ws[8ty+i][m] * x_m[m][4tx+j]
        #pragma unroll 2
        for (int mc = 0; mc < 128; mc += 4) {
            float wr[8][4];
            #pragma unroll
            for (int i = 0; i < 8; i++) {
                float4 w4 = *reinterpret_cast<const float4*>(&Ws[(8 * ty + i) * SN + mc]);
                wr[i][0] = w4.x; wr[i][1] = w4.y; wr[i][2] = w4.z; wr[i][3] = w4.w;
            }
            #pragma unroll
            for (int mm = 0; mm < 4; mm++) {
                float4 bb = *reinterpret_cast<const float4*>(&Xm2[(mc + mm) * SD + 4 * tx]);
                float bf[4] = {bb.x, bb.y, bb.z, bb.w};
                #pragma unroll
                for (int i = 0; i < 8; i++)
                    #pragma unroll
                    for (int j = 0; j < 4; j++)
                        acc[i][j] = fmaf(wr[i][mm], bf[j], acc[i][j]);
            }
        }
    }

    // Row-sum reduction over the 16 tx lanes sharing each row.
    #pragma unroll
    for (int i = 0; i < 8; i++) {
        float v = rs[i];
        v += __shfl_xor_sync(0xffffffffu, v, 1);
        v += __shfl_xor_sync(0xffffffffu, v, 2);
        v += __shfl_xor_sync(0xffffffffu, v, 4);
        v += __shfl_xor_sync(0xffffffffu, v, 8);
        rs[i] = 1.0f / v;
    }

    #pragma unroll
    for (int i = 0; i < 8; i++) {
        float4 o;
        o.x = acc[i][0] * rs[i];
        o.y = acc[i][1] * rs[i];
        o.z = acc[i][2] * rs[i];
        o.w = acc[i][3] * rs[i];
        *reinterpret_cast<float4*>(
            out + (size_t)(b * N + n0 + 8 * ty + i) * D + 4 * tx) = o;
    }
}

extern "C" void kernel_launch(void* const* d_in, const int* in_sizes, int n_in,
                              void* d_out, int out_size) {
    const float* x    = (const float*)d_in[0];
    const float* adj  = (const float*)d_in[1];
    const float* beta = (const float*)d_in[2];
    float* out = (float*)d_out;

    prep_kernel<<<B * N / 8, NTHREADS>>>(x);

    cudaFuncSetAttribute(attn_kernel,
                         cudaFuncAttributeMaxDynamicSharedMemorySize, SMEM_BYTES);
    dim3 grid(N / BN, B);
    attn_kernel<<<grid, NTHREADS, SMEM_BYTES>>>(x, adj, beta, out);
}